// round 10
// baseline (speedup 1.0000x reference)
#include <cuda_runtime.h>
#include <cstdint>

// NAIS scoring, per-WARP private cp.async pipeline (resubmit of R9 after
// transient GB300 container failure; deadlock audit passed: group accounting
// is uniform, single pre-loop CTA barrier, smem under cap).
//
//   qp[d]  = bias[h,d] + sum_e Q[b,h,e] * Wc[h,e,d]            (fp32, exact)
//   out[k] = sum_d relu( qp[d] + (K[k,:] @ Wk)[d] ) * Wo[h,d]  (K@Wk in tf32)
//
// m16n8k8 fragments (g = lane>>2, c = lane&3):
//   A: a0=(g,s0) a1=(g+8,s0) a2=(g,s1) a3=(g+8,s1);  B: b0=(s0,n=g) b1=(s1,n=g)
//   C: c0=(g,2c) c1=(g,2c+1) c2=(g+8,2c) c3=(g+8,2c+1)
// Line-dense column permutation (same bijection on A and B), step s:
//   slot0 -> col 16*(s>>1) + 4c + 2*(s&1), slot1 -> +1
//
// Pipeline (NO CTA barriers in the main loop): each warp owns a 3-deep ring
// of 32-row stages (8 KB each) and its own cp.async group stream:
//   fill(st+2) -> wait_group 2 -> syncwarp -> compute(st).
// Smem stage layout: row r at r*256 B; 16B slot q at (16q) ^ ((r&1)<<6) ->
// cp.async writes and LDS.128 reads are bank-conflict-free.

namespace {
constexpr int Bc = 32, Hc = 8, KL = 8192, Dd = 64;
constexpr int NTHREADS = 256;                  // 8 warps
constexpr int WARPS    = 8;
constexpr int SROWS    = 32;                   // rows per warp-stage
constexpr int NS       = 8;                    // stages per warp
constexpr int DEPTH    = 3;                    // ring depth
constexpr int STAGE_BYTES = SROWS * 256;       // 8192
constexpr int WARP_BYTES  = DEPTH * STAGE_BYTES;       // 24576
constexpr int KCHUNK   = WARPS * SROWS * NS;   // 2048 rows per CTA

constexpr int OFF_BP     = WARPS * WARP_BYTES;         // 196608
constexpr int OFF_QPS    = OFF_BP + 8 * 8 * 32 * 8;    // +16384
constexpr int OFF_WOS    = OFF_QPS + 256;
constexpr int SMEM_TOTAL = OFF_WOS + 256;              // 213504 B -> 1 CTA/SM
}

__device__ __forceinline__ uint32_t f2tf(float f) {
    uint32_t r;
    asm("cvt.rna.tf32.f32 %0, %1;" : "=r"(r) : "f"(f));
    return r;
}

__device__ __forceinline__ uint32_t smem_u32(const void* p) {
    uint32_t a;
    asm("{ .reg .u64 t; cvta.to.shared.u64 t, %1; cvt.u32.u64 %0, t; }" : "=r"(a) : "l"(p));
    return a;
}

__device__ __forceinline__ void cp_async16(uint32_t saddr, const void* gaddr) {
    asm volatile("cp.async.cg.shared.global [%0], [%1], 16;" :: "r"(saddr), "l"(gaddr));
}
#define CP_COMMIT() asm volatile("cp.async.commit_group;" ::: "memory")

__device__ __forceinline__ void mma_tf32(float c[4],
                                         uint32_t a0, uint32_t a1, uint32_t a2, uint32_t a3,
                                         uint32_t b0, uint32_t b1) {
    asm volatile(
        "mma.sync.aligned.m16n8k8.row.col.f32.tf32.tf32.f32 "
        "{%0,%1,%2,%3}, {%4,%5,%6,%7}, {%8,%9}, {%0,%1,%2,%3};"
        : "+f"(c[0]), "+f"(c[1]), "+f"(c[2]), "+f"(c[3])
        : "r"(a0), "r"(a1), "r"(a2), "r"(a3), "r"(b0), "r"(b1));
}

__global__ void __launch_bounds__(NTHREADS, 1)
nais_wp_kernel(const float* __restrict__ Q, const float* __restrict__ K,
               const float* __restrict__ Wc, const float* __restrict__ Wo,
               const float* __restrict__ bias, float* __restrict__ out)
{
    extern __shared__ __align__(16) char smem[];
    const uint32_t sb = smem_u32(smem);
    uint2* Bp  = reinterpret_cast<uint2*>(smem + OFF_BP);
    float* qps = reinterpret_cast<float*>(smem + OFF_QPS);
    float* wos = reinterpret_cast<float*>(smem + OFF_WOS);

    const int tid  = threadIdx.x;
    const int w    = tid >> 5;
    const int lane = tid & 31;
    const int c    = lane & 3;
    const int g    = lane >> 2;

    const int bid   = blockIdx.x;
    const int bh    = bid >> 2;                // b*H + h
    const int chunk = bid & 3;
    const int h     = bh & (Hc - 1);

    const float* __restrict__ WcH = Wc + (size_t)h * 2 * Dd * Dd;
    const float* __restrict__ Wk  = WcH + Dd * Dd;
    const float* __restrict__ Kc  = K + (size_t)bh * KL * Dd + (size_t)chunk * KCHUNK * Dd;
    float* __restrict__ outp = out + (size_t)bh * KL + (size_t)chunk * KCHUNK;

    // warp-private row range and smem ring
    const float* __restrict__ warpKc = Kc + (size_t)(w * SROWS * NS) * Dd;
    float* __restrict__ outw = outp + w * SROWS * NS;
    const uint32_t wbase = sb + w * WARP_BYTES;

    // fill stage st_ into ring buffer buf_: 16 x 16B per thread, coalesced gmem
    #define FILL(st_, buf_) do {                                                   \
        const float* _src = warpKc + (size_t)(st_) * SROWS * Dd;                   \
        const uint32_t _dst = wbase + (buf_) * STAGE_BYTES;                        \
        _Pragma("unroll")                                                          \
        for (int _i = 0; _i < 16; _i++) {                                          \
            int _ch = _i * 32 + lane;          /* 0..511 */                        \
            int _r = _ch >> 4, _q = _ch & 15;                                      \
            cp_async16(_dst + _r * 256 + ((_q * 16) ^ ((_r & 1) << 6)),            \
                       _src + (size_t)_r * Dd + _q * 4);                           \
        }                                                                          \
        CP_COMMIT();                                                               \
    } while (0)

    // prime the pipeline before the prologue (overlap with Bp packing)
    FILL(0, 0);
    FILL(1, 1);

    // ---- prologue: Bp pack (line-dense map), qp, wo ----
    #pragma unroll
    for (int i = 0; i < (8 * 8 * 32) / NTHREADS; i++) {
        int idx = tid + i * NTHREADS;          // ((nt*8 + s)*32 + ln)
        int ln = idx & 31, s = (idx >> 5) & 7, nt = idx >> 8;
        int cc = ln & 3, gg = ln >> 2;
        int e0 = 16 * (s >> 1) + 4 * cc + 2 * (s & 1);
        int n  = nt * 8 + gg;
        Bp[idx] = make_uint2(f2tf(Wk[e0 * Dd + n]), f2tf(Wk[(e0 + 1) * Dd + n]));
    }
    if (tid < Dd) {
        wos[tid] = Wo[h * Dd + tid];
        float acc = bias[h * Dd + tid];
        const float* __restrict__ q = Q + (size_t)bh * Dd;
        #pragma unroll 8
        for (int e = 0; e < Dd; e++) acc = fmaf(q[e], WcH[e * Dd + tid], acc);
        qps[tid] = acc;
    }
    __syncthreads();                           // only CTA barrier in the kernel

    const uint32_t xorv = (uint32_t)((g & 1) << 6);
    int bcur = 0, bfill = 2;

    for (int st = 0; st < NS; st++) {
        // keep one group per iteration for uniform wait_group accounting
        if (st + 2 < NS) { FILL(st + 2, bfill); }
        else             { CP_COMMIT(); }
        bfill = (bfill == DEPTH - 1) ? 0 : bfill + 1;

        asm volatile("cp.async.wait_group 2;" ::: "memory");
        __syncwarp();

        // ---- A fragments from private smem (conflict-free LDS.128) ----
        const uint32_t abase = wbase + bcur * STAGE_BYTES;
        uint32_t A[2][2][16];
        #pragma unroll
        for (int rt = 0; rt < 2; rt++)
            #pragma unroll
            for (int hf = 0; hf < 2; hf++) {
                const uint32_t rowb = abase + (rt * 16 + hf * 8 + g) * 256;
                #pragma unroll
                for (int j = 0; j < 4; j++) {
                    uint32_t x, y, z, u;
                    asm volatile("ld.shared.v4.b32 {%0,%1,%2,%3}, [%4];"
                                 : "=r"(x), "=r"(y), "=r"(z), "=r"(u)
                                 : "r"(rowb + (((uint32_t)(j * 64 + c * 16)) ^ xorv)));
                    A[rt][hf][4 * j + 0] = f2tf(__uint_as_float(x));
                    A[rt][hf][4 * j + 1] = f2tf(__uint_as_float(y));
                    A[rt][hf][4 * j + 2] = f2tf(__uint_as_float(z));
                    A[rt][hf][4 * j + 3] = f2tf(__uint_as_float(u));
                }
            }
        bcur = (bcur == DEPTH - 1) ? 0 : bcur + 1;

        // ---- 128 mma, b shared across both 16-row halves (R7 ratio) ----
        float psum[2][2] = {{0.f, 0.f}, {0.f, 0.f}};
        #pragma unroll
        for (int nt = 0; nt < 8; nt++) {
            const float qp0 = qps[nt * 8 + 2 * c], qp1 = qps[nt * 8 + 2 * c + 1];
            const float w0  = wos[nt * 8 + 2 * c], w1  = wos[nt * 8 + 2 * c + 1];

            float acc0[4] = {0.f, 0.f, 0.f, 0.f};
            float acc1[4] = {0.f, 0.f, 0.f, 0.f};
            #pragma unroll
            for (int s = 0; s < 8; s++) {
                const uint2 b = Bp[(nt * 8 + s) * 32 + lane];
                mma_tf32(acc0, A[0][0][2 * s], A[0][1][2 * s],
                               A[0][0][2 * s + 1], A[0][1][2 * s + 1], b.x, b.y);
                mma_tf32(acc1, A[1][0][2 * s], A[1][1][2 * s],
                               A[1][0][2 * s + 1], A[1][1][2 * s + 1], b.x, b.y);
            }
            psum[0][0] += fmaxf(acc0[0] + qp0, 0.f) * w0 + fmaxf(acc0[1] + qp1, 0.f) * w1;
            psum[0][1] += fmaxf(acc0[2] + qp0, 0.f) * w0 + fmaxf(acc0[3] + qp1, 0.f) * w1;
            psum[1][0] += fmaxf(acc1[0] + qp0, 0.f) * w0 + fmaxf(acc1[1] + qp1, 0.f) * w1;
            psum[1][1] += fmaxf(acc1[2] + qp0, 0.f) * w0 + fmaxf(acc1[3] + qp1, 0.f) * w1;
        }

        // ---- reduce over 4 lanes per group, store ----
        #pragma unroll
        for (int rt = 0; rt < 2; rt++)
            #pragma unroll
            for (int hf = 0; hf < 2; hf++) {
                float p = psum[rt][hf];
                p += __shfl_xor_sync(0xffffffffu, p, 1);
                p += __shfl_xor_sync(0xffffffffu, p, 2);
                if (c == 0)
                    outw[st * SROWS + rt * 16 + hf * 8 + g] = p;
            }
    }
    #undef FILL
}

extern "C" void kernel_launch(void* const* d_in, const int* in_sizes, int n_in,
                              void* d_out, int out_size)
{
    const float* Q    = (const float*)d_in[0];
    const float* K    = (const float*)d_in[1];
    const float* Wc   = (const float*)d_in[2];
    const float* Wo   = (const float*)d_in[3];
    const float* bias = (const float*)d_in[4];
    float* out = (float*)d_out;

    cudaFuncSetAttribute(nais_wp_kernel,
                         cudaFuncAttributeMaxDynamicSharedMemorySize, SMEM_TOTAL);

    const int grid = Bc * Hc * (KL / KCHUNK);   // 1024 blocks
    nais_wp_kernel<<<grid, NTHREADS, SMEM_TOTAL>>>(Q, K, Wc, Wo, bias, out);
}

// round 11
// speedup vs baseline: 1.1736x; 1.1736x over previous
#include <cuda_runtime.h>
#include <cstdint>

// NAIS scoring via warp-level tf32 mma.sync (R7 structure, de-cvt'd mainloop).
//
//   qp[d]  = bias[h,d] + sum_e Q[b,h,e] * Wc[h,e,d]            (fp32, exact)
//   out[k] = sum_d relu( qp[d] + (K[k,:] @ Wk)[d] ) * Wo[h,d]  (K@Wk in tf32)
//
// m16n8k8 fragments (g = lane>>2, c = lane&3):
//   A: a0=(g,s0) a1=(g+8,s0) a2=(g,s1) a3=(g+8,s1);  B: b0=(s0,n=g) b1=(s1,n=g)
//   C: c0=(g,2c) c1=(g,2c+1) c2=(g+8,2c) c3=(g+8,2c+1)
// Line-dense column permutation (same bijection on A and B), step s = 2j+t:
//   slot0 -> col 16j + 4c + 2t, slot1 -> +1; thread's j-th float4 = row bytes
//   [64j+16c, +16) -> each LDG.128 touches 8 lines (R7's replay fix, kept).
//
// R11 deltas vs R7 (133.6us):
//   1) A operands passed to mma as RAW fp32 bits (tensor path reads
//      sign/exp/10-mantissa; RZ truncation) -> 128 cvt/warp-iter removed and
//      the LDG->cvt->mma chain shortened. B stays rna-converted in prologue.
//   2) Bp packed as uint4 (k-steps 2j,2j+1 together; e-range [16j+4c,+4)):
//      32 LDS.128 instead of 64 LDS.64 (half the LDS issue slots).
//   3) KCHUNK 1024 (grid 2048): last wave 92% full instead of 46%.

namespace {
constexpr int Bc = 32, Hc = 8, KL = 8192, Dd = 64;
constexpr int NTHREADS = 256;                 // 8 warps
constexpr int KCHUNK   = 1024;                // rows per block
constexpr int ROWS_PER_ITER = 256;            // 8 warps x 32 rows
constexpr int NITER    = KCHUNK / ROWS_PER_ITER;  // 4
}

__device__ __forceinline__ uint32_t f2tf(float f) {
    uint32_t r;
    asm("cvt.rna.tf32.f32 %0, %1;" : "=r"(r) : "f"(f));
    return r;
}

__device__ __forceinline__ void mma_tf32(float c[4],
                                         uint32_t a0, uint32_t a1, uint32_t a2, uint32_t a3,
                                         uint32_t b0, uint32_t b1) {
    asm volatile(
        "mma.sync.aligned.m16n8k8.row.col.f32.tf32.tf32.f32 "
        "{%0,%1,%2,%3}, {%4,%5,%6,%7}, {%8,%9}, {%0,%1,%2,%3};"
        : "+f"(c[0]), "+f"(c[1]), "+f"(c[2]), "+f"(c[3])
        : "r"(a0), "r"(a1), "r"(a2), "r"(a3), "r"(b0), "r"(b1));
}

__global__ void __launch_bounds__(NTHREADS, 2)
nais_mma_kernel(const float* __restrict__ Q, const float* __restrict__ K,
                const float* __restrict__ Wc, const float* __restrict__ Wo,
                const float* __restrict__ bias, float* __restrict__ out)
{
    // Bp4[(nt*4 + j)*32 + lane] = { tf32 Wk[e0..e0+3][n] }, e0 = 16j + 4c, n = nt*8 + g
    //   (.x,.y = k-step 2j slots 0/1 ; .z,.w = k-step 2j+1 slots 0/1)
    __shared__ uint4 Bp4[8 * 4 * 32];         // 16 KB
    __shared__ float qps[Dd], wos[Dd];

    const int tid  = threadIdx.x;
    const int w    = tid >> 5;
    const int lane = tid & 31;
    const int c    = lane & 3;                // threadID_in_group
    const int g    = lane >> 2;               // groupID

    const int bid   = blockIdx.x;
    const int bh    = bid >> 3;               // b*H + h
    const int chunk = bid & 7;
    const int h     = bh & (Hc - 1);

    const float* __restrict__ WcH = Wc + (size_t)h * 2 * Dd * Dd;
    const float* __restrict__ Wk  = WcH + Dd * Dd;    // bottom half: [e][d]
    const float* __restrict__ Kc  = K + (size_t)bh * KL * Dd + (size_t)chunk * KCHUNK * Dd;
    float* __restrict__ outp = out + (size_t)bh * KL + (size_t)chunk * KCHUNK;

    // ---- prologue ----
    #pragma unroll
    for (int i = 0; i < (8 * 4 * 32) / NTHREADS; i++) {   // 4 packs/thread
        int idx = tid + i * NTHREADS;          // ((nt*4 + j)*32 + ln)
        int ln = idx & 31, j = (idx >> 5) & 3, nt = idx >> 7;
        int cc = ln & 3, gg = ln >> 2;
        int e0 = 16 * j + 4 * cc;
        int n  = nt * 8 + gg;
        Bp4[idx] = make_uint4(f2tf(Wk[(e0 + 0) * Dd + n]), f2tf(Wk[(e0 + 1) * Dd + n]),
                              f2tf(Wk[(e0 + 2) * Dd + n]), f2tf(Wk[(e0 + 3) * Dd + n]));
    }
    if (tid < Dd) {                            // qp = bias + Q @ Wq (fp32 exact); wo
        wos[tid] = Wo[h * Dd + tid];
        float acc = bias[h * Dd + tid];
        const float* __restrict__ q = Q + (size_t)bh * Dd;
        #pragma unroll 8
        for (int e = 0; e < Dd; e++) acc = fmaf(q[e], WcH[e * Dd + tid], acc);
        qps[tid] = acc;
    }
    __syncthreads();

    // ---- main loop: 32 rows per warp per iter, A straight from GMEM (raw bits) ----
    for (int it = 0; it < NITER; it++) {
        const int rowbase = it * ROWS_PER_ITER + w * 32;

        // A[rt][hf][4j+u] = raw fp32 bits of row (rowbase+rt*16+hf*8+g), col 16j+4c+u
        uint32_t A[2][2][16];
        #pragma unroll
        for (int rt = 0; rt < 2; rt++)
            #pragma unroll
            for (int hf = 0; hf < 2; hf++) {
                const int r = rowbase + rt * 16 + hf * 8 + g;
                const uint4* p = reinterpret_cast<const uint4*>(Kc + (size_t)r * Dd);
                uint4 f0 = p[c], f1 = p[4 + c], f2 = p[8 + c], f3 = p[12 + c];
                A[rt][hf][0]  = f0.x; A[rt][hf][1]  = f0.y;
                A[rt][hf][2]  = f0.z; A[rt][hf][3]  = f0.w;
                A[rt][hf][4]  = f1.x; A[rt][hf][5]  = f1.y;
                A[rt][hf][6]  = f1.z; A[rt][hf][7]  = f1.w;
                A[rt][hf][8]  = f2.x; A[rt][hf][9]  = f2.y;
                A[rt][hf][10] = f2.z; A[rt][hf][11] = f2.w;
                A[rt][hf][12] = f3.x; A[rt][hf][13] = f3.y;
                A[rt][hf][14] = f3.z; A[rt][hf][15] = f3.w;
            }

        float psum[2][2] = {{0.f, 0.f}, {0.f, 0.f}};

        #pragma unroll
        for (int nt = 0; nt < 8; nt++) {
            const float qp0 = qps[nt * 8 + 2 * c], qp1 = qps[nt * 8 + 2 * c + 1];
            const float w0  = wos[nt * 8 + 2 * c], w1  = wos[nt * 8 + 2 * c + 1];

            float acc0[4] = {0.f, 0.f, 0.f, 0.f};
            float acc1[4] = {0.f, 0.f, 0.f, 0.f};

            #pragma unroll
            for (int j = 0; j < 4; j++) {
                const uint4 bb = Bp4[(nt * 4 + j) * 32 + lane];
                // k-step s = 2j   : A[4j],   A[4j+1]  x  (bb.x, bb.y)
                mma_tf32(acc0, A[0][0][4 * j],     A[0][1][4 * j],
                               A[0][0][4 * j + 1], A[0][1][4 * j + 1], bb.x, bb.y);
                mma_tf32(acc1, A[1][0][4 * j],     A[1][1][4 * j],
                               A[1][0][4 * j + 1], A[1][1][4 * j + 1], bb.x, bb.y);
                // k-step s = 2j+1 : A[4j+2], A[4j+3]  x  (bb.z, bb.w)
                mma_tf32(acc0, A[0][0][4 * j + 2], A[0][1][4 * j + 2],
                               A[0][0][4 * j + 3], A[0][1][4 * j + 3], bb.z, bb.w);
                mma_tf32(acc1, A[1][0][4 * j + 2], A[1][1][4 * j + 2],
                               A[1][0][4 * j + 3], A[1][1][4 * j + 3], bb.z, bb.w);
            }
            psum[0][0] += fmaxf(acc0[0] + qp0, 0.f) * w0 + fmaxf(acc0[1] + qp1, 0.f) * w1;
            psum[0][1] += fmaxf(acc0[2] + qp0, 0.f) * w0 + fmaxf(acc0[3] + qp1, 0.f) * w1;
            psum[1][0] += fmaxf(acc1[0] + qp0, 0.f) * w0 + fmaxf(acc1[1] + qp1, 0.f) * w1;
            psum[1][1] += fmaxf(acc1[2] + qp0, 0.f) * w0 + fmaxf(acc1[3] + qp1, 0.f) * w1;
        }

        // reduce over the 4 lanes of each group (c = 0..3), then store
        #pragma unroll
        for (int rt = 0; rt < 2; rt++)
            #pragma unroll
            for (int hf = 0; hf < 2; hf++) {
                float p = psum[rt][hf];
                p += __shfl_xor_sync(0xffffffffu, p, 1);
                p += __shfl_xor_sync(0xffffffffu, p, 2);
                if (c == 0)
                    outp[rowbase + rt * 16 + hf * 8 + g] = p;
            }
    }
}

extern "C" void kernel_launch(void* const* d_in, const int* in_sizes, int n_in,
                              void* d_out, int out_size)
{
    const float* Q    = (const float*)d_in[0];
    const float* K    = (const float*)d_in[1];
    const float* Wc   = (const float*)d_in[2];
    const float* Wo   = (const float*)d_in[3];
    const float* bias = (const float*)d_in[4];
    float* out = (float*)d_out;

    const int grid = Bc * Hc * (KL / KCHUNK);   // 2048 blocks
    nais_mma_kernel<<<grid, NTHREADS>>>(Q, K, Wc, Wo, bias, out);
}

// round 12
// speedup vs baseline: 1.1817x; 1.0069x over previous
#include <cuda_runtime.h>
#include <cuda_fp16.h>
#include <cstdint>

// NAIS scoring via warp-level fp16 mma.sync m16n8k16 (occupancy play).
//
//   qp[d]  = bias[h,d] + sum_e Q[b,h,e] * Wc[h,e,d]            (fp32, exact)
//   out[k] = sum_d relu( qp[d] + (K[k,:] @ Wk)[d] ) * Wo[h,d]  (K@Wk in fp16 x fp16 -> fp32)
//
// Why fp16: same 10-bit mantissa as tf32 (rel_err band unchanged), but 2
// elements/register -> A fragments for 32 rows shrink 64->32 regs, mma count
// 128->64, Bp LDS.128->LDS.64. Live set ~75 regs => __launch_bounds__(256,3)
// = 24 warps/SM (was 16 at regs=128). The R4..R11 invariant was DRAM ~51%
// bound by per-warp exposed LDG latency at 16 warps; +50% warps is the lever.
//
// m16n8k16 fragments (g = lane>>2, c = lane&3), reg = f16x2 (low = 1st elem):
//   A: a0={(g,2c),(g,2c+1)} a1={(g+8,2c),..} a2={(g,2c+8),(g,2c+9)} a3={(g+8,2c+8),..}
//   B: b0={(k 2c,n=g),(k 2c+1,n=g)} b1={(k 2c+8,n=g),(k 2c+9,n=g)}
//   C: c0=(g,2c) c1=(g,2c+1) c2=(g+8,2c) c3=(g+8,2c+1)
// Column permutation (same bijection on A and B), k-tile j (16 logical cols):
//   logical (2c,2c+1)   -> physical cols 16j+4c,   16j+4c+1
//   logical (2c+8,2c+9) -> physical cols 16j+4c+2, 16j+4c+3
// => thread's j-th float4 (row bytes [64j+16c,+16), line-dense as in R7) maps
//    to a0/a1 = pack(x,y), a2/a3 = pack(z,w).

namespace {
constexpr int Bc = 32, Hc = 8, KL = 8192, Dd = 64;
constexpr int NTHREADS = 256;                 // 8 warps
constexpr int KCHUNK   = 1024;                // rows per block
constexpr int ROWS_PER_ITER = 256;            // 8 warps x 32 rows
constexpr int NITER    = KCHUNK / ROWS_PER_ITER;  // 4
}

__device__ __forceinline__ uint32_t h2(float lo, float hi) {
    __half2 v = __floats2half2_rn(lo, hi);    // .x = lo (low 16 bits)
    return *reinterpret_cast<uint32_t*>(&v);
}

__device__ __forceinline__ void mma_f16(float c[4],
                                        uint32_t a0, uint32_t a1, uint32_t a2, uint32_t a3,
                                        uint32_t b0, uint32_t b1) {
    asm volatile(
        "mma.sync.aligned.m16n8k16.row.col.f32.f16.f16.f32 "
        "{%0,%1,%2,%3}, {%4,%5,%6,%7}, {%8,%9}, {%0,%1,%2,%3};"
        : "+f"(c[0]), "+f"(c[1]), "+f"(c[2]), "+f"(c[3])
        : "r"(a0), "r"(a1), "r"(a2), "r"(a3), "r"(b0), "r"(b1));
}

__global__ void __launch_bounds__(NTHREADS, 3)
nais_h16_kernel(const float* __restrict__ Q, const float* __restrict__ K,
                const float* __restrict__ Wc, const float* __restrict__ Wo,
                const float* __restrict__ bias, float* __restrict__ out)
{
    // Bp2[(nt*4 + j)*32 + lane] = { h2(Wk[e0][n],Wk[e0+1][n]), h2(Wk[e0+2][n],Wk[e0+3][n]) }
    //   e0 = 16j + 4c, n = nt*8 + g   (.x = b0, .y = b1)
    __shared__ uint2 Bp2[8 * 4 * 32];         // 8 KB
    __shared__ float qps[Dd], wos[Dd];

    const int tid  = threadIdx.x;
    const int w    = tid >> 5;
    const int lane = tid & 31;
    const int c    = lane & 3;                // threadID_in_group
    const int g    = lane >> 2;               // groupID

    const int bid   = blockIdx.x;
    const int bh    = bid >> 3;               // b*H + h
    const int chunk = bid & 7;
    const int h     = bh & (Hc - 1);

    const float* __restrict__ WcH = Wc + (size_t)h * 2 * Dd * Dd;
    const float* __restrict__ Wk  = WcH + Dd * Dd;    // bottom half: [e][d]
    const float* __restrict__ Kc  = K + (size_t)bh * KL * Dd + (size_t)chunk * KCHUNK * Dd;
    float* __restrict__ outp = out + (size_t)bh * KL + (size_t)chunk * KCHUNK;

    // ---- prologue ----
    #pragma unroll
    for (int i = 0; i < (8 * 4 * 32) / NTHREADS; i++) {   // 4 packs/thread
        int idx = tid + i * NTHREADS;          // ((nt*4 + j)*32 + ln)
        int ln = idx & 31, j = (idx >> 5) & 3, nt = idx >> 7;
        int cc = ln & 3, gg = ln >> 2;
        int e0 = 16 * j + 4 * cc;
        int n  = nt * 8 + gg;
        Bp2[idx] = make_uint2(h2(Wk[(e0 + 0) * Dd + n], Wk[(e0 + 1) * Dd + n]),
                              h2(Wk[(e0 + 2) * Dd + n], Wk[(e0 + 3) * Dd + n]));
    }
    if (tid < Dd) {                            // qp = bias + Q @ Wq (fp32 exact); wo
        wos[tid] = Wo[h * Dd + tid];
        float acc = bias[h * Dd + tid];
        const float* __restrict__ q = Q + (size_t)bh * Dd;
        #pragma unroll 8
        for (int e = 0; e < Dd; e++) acc = fmaf(q[e], WcH[e * Dd + tid], acc);
        qps[tid] = acc;
    }
    __syncthreads();

    // ---- main loop: 32 rows per warp per iter, A from GMEM, packed to f16x2 ----
    for (int it = 0; it < NITER; it++) {
        const int rowbase = it * ROWS_PER_ITER + w * 32;

        // A[rt][hf][j][0] = pack(cols 16j+4c, +1), [1] = pack(cols 16j+4c+2, +3)
        uint32_t A[2][2][4][2];
        #pragma unroll
        for (int rt = 0; rt < 2; rt++)
            #pragma unroll
            for (int hf = 0; hf < 2; hf++) {
                const int r = rowbase + rt * 16 + hf * 8 + g;
                const float4* p = reinterpret_cast<const float4*>(Kc + (size_t)r * Dd);
                #pragma unroll
                for (int j = 0; j < 4; j++) {
                    float4 f = p[4 * j + c];
                    A[rt][hf][j][0] = h2(f.x, f.y);
                    A[rt][hf][j][1] = h2(f.z, f.w);
                }
            }

        float psum[2][2] = {{0.f, 0.f}, {0.f, 0.f}};

        #pragma unroll
        for (int nt = 0; nt < 8; nt++) {
            const float qp0 = qps[nt * 8 + 2 * c], qp1 = qps[nt * 8 + 2 * c + 1];
            const float w0  = wos[nt * 8 + 2 * c], w1  = wos[nt * 8 + 2 * c + 1];

            float acc0[4] = {0.f, 0.f, 0.f, 0.f};
            float acc1[4] = {0.f, 0.f, 0.f, 0.f};

            #pragma unroll
            for (int j = 0; j < 4; j++) {
                const uint2 bb = Bp2[(nt * 4 + j) * 32 + lane];
                mma_f16(acc0, A[0][0][j][0], A[0][1][j][0],
                              A[0][0][j][1], A[0][1][j][1], bb.x, bb.y);
                mma_f16(acc1, A[1][0][j][0], A[1][1][j][0],
                              A[1][0][j][1], A[1][1][j][1], bb.x, bb.y);
            }
            psum[0][0] += fmaxf(acc0[0] + qp0, 0.f) * w0 + fmaxf(acc0[1] + qp1, 0.f) * w1;
            psum[0][1] += fmaxf(acc0[2] + qp0, 0.f) * w0 + fmaxf(acc0[3] + qp1, 0.f) * w1;
            psum[1][0] += fmaxf(acc1[0] + qp0, 0.f) * w0 + fmaxf(acc1[1] + qp1, 0.f) * w1;
            psum[1][1] += fmaxf(acc1[2] + qp0, 0.f) * w0 + fmaxf(acc1[3] + qp1, 0.f) * w1;
        }

        // reduce over the 4 lanes of each group (c = 0..3), then store
        #pragma unroll
        for (int rt = 0; rt < 2; rt++)
            #pragma unroll
            for (int hf = 0; hf < 2; hf++) {
                float p = psum[rt][hf];
                p += __shfl_xor_sync(0xffffffffu, p, 1);
                p += __shfl_xor_sync(0xffffffffu, p, 2);
                if (c == 0)
                    outp[rowbase + rt * 16 + hf * 8 + g] = p;
            }
    }
}

extern "C" void kernel_launch(void* const* d_in, const int* in_sizes, int n_in,
                              void* d_out, int out_size)
{
    const float* Q    = (const float*)d_in[0];
    const float* K    = (const float*)d_in[1];
    const float* Wc   = (const float*)d_in[2];
    const float* Wo   = (const float*)d_in[3];
    const float* bias = (const float*)d_in[4];
    float* out = (float*)d_out;

    const int grid = Bc * Hc * (KL / KCHUNK);   // 2048 blocks
    nais_h16_kernel<<<grid, NTHREADS>>>(Q, K, Wc, Wo, bias, out);
}

// round 13
// speedup vs baseline: 1.5687x; 1.3275x over previous
#include <cuda_runtime.h>
#include <cuda_fp16.h>
#include <cstdint>

// NAIS scoring via warp-level fp16 mma.sync m16n8k16, 512-thread CTAs
// (32 warps/SM at 2 CTAs x 64 regs = full register file).
//
//   qp[d]  = bias[h,d] + sum_e Q[b,h,e] * Wc[h,e,d]            (fp32, exact)
//   out[k] = sum_d relu( qp[d] + (K[k,:] @ Wk)[d] ) * Wo[h,d]
//
// m16n8k16 fragments (g = lane>>2, c = lane&3), reg = f16x2 (low = 1st elem):
//   A: a0={(g,2c),(g,2c+1)} a1={(g+8,2c),..} a2={(g,2c+8),(g,2c+9)} a3={(g+8,..)}
//   B: b0={(k 2c,n=g),(k 2c+1,n=g)} b1={(k 2c+8,n=g),(k 2c+9,n=g)}
//   C: c0=(g,2c) c1=(g,2c+1) c2=(g+8,2c) c3=(g+8,2c+1)
// Column permutation (same bijection on A and B), k-tile j:
//   logical (2c,2c+1) -> cols 16j+4c,+1 ; logical (2c+8,2c+9) -> 16j+4c+2,+3
// => thread's j-th float4 (line-dense, row bytes [64j+16c,+16)) packs to
//    a0/a1 = h2(x,y), a2/a3 = h2(z,w).  Identical math to R12 (rel 2.32e-4).
//
// R13 deltas vs R12 (133.9us, DRAM 49.5%, L1 73.1%, occ 35%):
//   1) 512-thread CTAs, __launch_bounds__(512,2): 24 -> 32 warps/SM. The
//      R7/R11/R12 plateau is L1tex-queue-inflated LDG latency; more warps
//      raise DRAM duty until L1 saturates (~93%).
//   2) qp/wo pre-paired float2 -> 16 LDS.64 instead of 32 LDS.32 / warp-iter.
//   3) B fragments as uint4 -> 16 LDS.128 instead of 32 LDS.64.
//   4) __ldcs on K (single-use stream).

namespace {
constexpr int Bc = 32, Hc = 8, KL = 8192, Dd = 64;
constexpr int NTHREADS = 512;                 // 16 warps
constexpr int KCHUNK   = 1024;                // rows per block
constexpr int ROWS_PER_ITER = 512;            // 16 warps x 32 rows
constexpr int NITER    = KCHUNK / ROWS_PER_ITER;  // 2
}

__device__ __forceinline__ uint32_t h2(float lo, float hi) {
    __half2 v = __floats2half2_rn(lo, hi);    // .x = lo (low 16 bits)
    return *reinterpret_cast<uint32_t*>(&v);
}

__device__ __forceinline__ void mma_f16(float c[4],
                                        uint32_t a0, uint32_t a1, uint32_t a2, uint32_t a3,
                                        uint32_t b0, uint32_t b1) {
    asm volatile(
        "mma.sync.aligned.m16n8k16.row.col.f32.f16.f16.f32 "
        "{%0,%1,%2,%3}, {%4,%5,%6,%7}, {%8,%9}, {%0,%1,%2,%3};"
        : "+f"(c[0]), "+f"(c[1]), "+f"(c[2]), "+f"(c[3])
        : "r"(a0), "r"(a1), "r"(a2), "r"(a3), "r"(b0), "r"(b1));
}

__global__ void __launch_bounds__(NTHREADS, 2)
nais_h32_kernel(const float* __restrict__ Q, const float* __restrict__ K,
                const float* __restrict__ Wc, const float* __restrict__ Wo,
                const float* __restrict__ bias, float* __restrict__ out)
{
    // Bp4h[(nt*2 + jp)*32 + lane]: k-tiles j=2jp (.x,.y) and j=2jp+1 (.z,.w)
    //   .x = h2(Wk[e0][n],Wk[e0+1][n]), .y = h2(Wk[e0+2][n],Wk[e0+3][n]),
    //   e0 = 16j + 4c, n = nt*8 + g
    __shared__ uint4  Bp4h[8 * 2 * 32];       // 8 KB
    __shared__ float  qps[Dd], wos[Dd];
    __shared__ float2 qp2[32], wo2[32];       // [nt*4 + c] = (v[nt*8+2c], v[nt*8+2c+1])

    const int tid  = threadIdx.x;
    const int w    = tid >> 5;
    const int lane = tid & 31;
    const int c    = lane & 3;                // threadID_in_group
    const int g    = lane >> 2;               // groupID

    const int bid   = blockIdx.x;
    const int bh    = bid >> 3;               // b*H + h
    const int chunk = bid & 7;
    const int h     = bh & (Hc - 1);

    const float* __restrict__ WcH = Wc + (size_t)h * 2 * Dd * Dd;
    const float* __restrict__ Wk  = WcH + Dd * Dd;    // bottom half: [e][d]
    const float* __restrict__ Kc  = K + (size_t)bh * KL * Dd + (size_t)chunk * KCHUNK * Dd;
    float* __restrict__ outp = out + (size_t)bh * KL + (size_t)chunk * KCHUNK;

    // ---- prologue ----
    {   // one Bp4h entry per thread (512 entries)
        int ln = tid & 31, jp = (tid >> 5) & 1, nt = tid >> 6;
        int cc = ln & 3, gg = ln >> 2;
        int n  = nt * 8 + gg;
        int e0 = 16 * (2 * jp) + 4 * cc;
        int e1 = 16 * (2 * jp + 1) + 4 * cc;
        Bp4h[tid] = make_uint4(
            h2(Wk[(e0 + 0) * Dd + n], Wk[(e0 + 1) * Dd + n]),
            h2(Wk[(e0 + 2) * Dd + n], Wk[(e0 + 3) * Dd + n]),
            h2(Wk[(e1 + 0) * Dd + n], Wk[(e1 + 1) * Dd + n]),
            h2(Wk[(e1 + 2) * Dd + n], Wk[(e1 + 3) * Dd + n]));
    }
    if (tid < Dd) {                            // qp = bias + Q @ Wq (fp32 exact); wo
        wos[tid] = Wo[h * Dd + tid];
        float acc = bias[h * Dd + tid];
        const float* __restrict__ q = Q + (size_t)bh * Dd;
        #pragma unroll 8
        for (int e = 0; e < Dd; e++) acc = fmaf(q[e], WcH[e * Dd + tid], acc);
        qps[tid] = acc;
    }
    __syncthreads();
    if (tid < 64) {                            // pair for LDS.64 epilogue reads
        int i = tid & 31, nt = i >> 2, cc = i & 3;
        if (tid < 32) qp2[i] = make_float2(qps[nt * 8 + 2 * cc], qps[nt * 8 + 2 * cc + 1]);
        else          wo2[i] = make_float2(wos[nt * 8 + 2 * cc], wos[nt * 8 + 2 * cc + 1]);
    }
    __syncthreads();

    // ---- main loop: 32 rows per warp per iter, A from GMEM (streaming), fp16-packed ----
    for (int it = 0; it < NITER; it++) {
        const int rowbase = it * ROWS_PER_ITER + w * 32;

        // A[rt][hf][j][0] = pack(cols 16j+4c,+1), [1] = pack(cols 16j+4c+2,+3)
        uint32_t A[2][2][4][2];
        #pragma unroll
        for (int rt = 0; rt < 2; rt++)
            #pragma unroll
            for (int hf = 0; hf < 2; hf++) {
                const int r = rowbase + rt * 16 + hf * 8 + g;
                const float4* p = reinterpret_cast<const float4*>(Kc + (size_t)r * Dd);
                #pragma unroll
                for (int j = 0; j < 4; j++) {
                    float4 f = __ldcs(p + 4 * j + c);
                    A[rt][hf][j][0] = h2(f.x, f.y);
                    A[rt][hf][j][1] = h2(f.z, f.w);
                }
            }

        float psum[2][2] = {{0.f, 0.f}, {0.f, 0.f}};

        #pragma unroll
        for (int nt = 0; nt < 8; nt++) {
            const float2 qp = qp2[nt * 4 + c];
            const float2 wo = wo2[nt * 4 + c];

            float acc0[4] = {0.f, 0.f, 0.f, 0.f};
            float acc1[4] = {0.f, 0.f, 0.f, 0.f};

            #pragma unroll
            for (int jp = 0; jp < 2; jp++) {
                const uint4 bb = Bp4h[(nt * 2 + jp) * 32 + lane];
                const int j0 = 2 * jp, j1 = 2 * jp + 1;
                mma_f16(acc0, A[0][0][j0][0], A[0][1][j0][0],
                              A[0][0][j0][1], A[0][1][j0][1], bb.x, bb.y);
                mma_f16(acc1, A[1][0][j0][0], A[1][1][j0][0],
                              A[1][0][j0][1], A[1][1][j0][1], bb.x, bb.y);
                mma_f16(acc0, A[0][0][j1][0], A[0][1][j1][0],
                              A[0][0][j1][1], A[0][1][j1][1], bb.z, bb.w);
                mma_f16(acc1, A[1][0][j1][0], A[1][1][j1][0],
                              A[1][0][j1][1], A[1][1][j1][1], bb.z, bb.w);
            }
            psum[0][0] += fmaxf(acc0[0] + qp.x, 0.f) * wo.x + fmaxf(acc0[1] + qp.y, 0.f) * wo.y;
            psum[0][1] += fmaxf(acc0[2] + qp.x, 0.f) * wo.x + fmaxf(acc0[3] + qp.y, 0.f) * wo.y;
            psum[1][0] += fmaxf(acc1[0] + qp.x, 0.f) * wo.x + fmaxf(acc1[1] + qp.y, 0.f) * wo.y;
            psum[1][1] += fmaxf(acc1[2] + qp.x, 0.f) * wo.x + fmaxf(acc1[3] + qp.y, 0.f) * wo.y;
        }

        // reduce over the 4 lanes of each group (c = 0..3), then store
        #pragma unroll
        for (int rt = 0; rt < 2; rt++)
            #pragma unroll
            for (int hf = 0; hf < 2; hf++) {
                float p = psum[rt][hf];
                p += __shfl_xor_sync(0xffffffffu, p, 1);
                p += __shfl_xor_sync(0xffffffffu, p, 2);
                if (c == 0)
                    outp[rowbase + rt * 16 + hf * 8 + g] = p;
            }
    }
}

extern "C" void kernel_launch(void* const* d_in, const int* in_sizes, int n_in,
                              void* d_out, int out_size)
{
    const float* Q    = (const float*)d_in[0];
    const float* K    = (const float*)d_in[1];
    const float* Wc   = (const float*)d_in[2];
    const float* Wo   = (const float*)d_in[3];
    const float* bias = (const float*)d_in[4];
    float* out = (float*)d_out;

    const int grid = Bc * Hc * (KL / KCHUNK);   // 2048 blocks
    nais_h32_kernel<<<grid, NTHREADS>>>(Q, K, Wc, Wo, bias, out);
}